// round 4
// baseline (speedup 1.0000x reference)
#include <cuda_runtime.h>
#include <stdint.h>

#define NCOMP 256
#define PPB   8     // pairs per block
#define TPB   512   // two j-halves x 256 components

// Bit-packed tables indexed [ihi*256 + j], bit L refers to i = ihi*32 + L:
//   g_sgn: 1 iff sign(j, j^i) == -1
//   g_wed: 1 iff wedge term   (j subset of i)
//   g_inn: 1 iff inner term   ((j&i)==0 or i subset of j)
__device__ uint32_t g_sgn[8 * 256];
__device__ uint32_t g_wed[8 * 256];
__device__ uint32_t g_inn[8 * 256];

__global__ void build_tables_kernel() {
    int t    = blockIdx.x * blockDim.x + threadIdx.x;   // 0..65535
    int lane = t & 31;
    int j    = (t >> 5) & 255;
    int ihi  = t >> 13;
    int i    = (ihi << 5) | lane;
    int k    = j ^ i;
    int par  = 0;
#pragma unroll
    for (int d = 1; d < 8; ++d) par ^= __popc((j >> d) & k);
    unsigned ws = __ballot_sync(0xFFFFFFFFu, par & 1);
    unsigned ww = __ballot_sync(0xFFFFFFFFu, (j & ~i & 255) == 0);
    unsigned wi = __ballot_sync(0xFFFFFFFFu, ((j & i) == 0) || ((i & ~j & 255) == 0));
    if (lane == 0) {
        g_sgn[(ihi << 8) + j] = ws;
        g_wed[(ihi << 8) + j] = ww;
        g_inn[(ihi << 8) + j] = wi;
    }
}

__global__ __launch_bounds__(TPB, 1) void clifford_kernel(
    const float* __restrict__ A, const float* __restrict__ B,
    float* __restrict__ out, int npairs)
{
    // 40 KB pool:
    //   [0KB)  As0: float4[256]  pairs 0..3 of A at component j
    //   [4KB)  As1: float4[256]  pairs 4..7
    //   [8KB)  Bs0: float4[256]  pairs 0..3 of B
    //   [12KB) Bs1: float4[256]  pairs 4..7
    //   [16KB) Ssh  (reused as Red after loop), [24KB) Wsh, [32KB) Ish
    __shared__ __align__(16) unsigned char pool[40960];
    float4*   As0 = reinterpret_cast<float4*>(pool);
    float4*   As1 = reinterpret_cast<float4*>(pool + 4096);
    float4*   Bs0 = reinterpret_cast<float4*>(pool + 8192);
    float4*   Bs1 = reinterpret_cast<float4*>(pool + 12288);
    uint32_t* Ssh = reinterpret_cast<uint32_t*>(pool + 16384);
    uint32_t* Wsh = reinterpret_cast<uint32_t*>(pool + 24576);
    uint32_t* Ish = reinterpret_cast<uint32_t*>(pool + 32768);
    float4*   Red = reinterpret_cast<float4*>(pool + 16384);

    const int tid  = threadIdx.x;
    const int half = tid >> 8;       // 0: j in [0,128)   1: j in [128,256)
    const int i    = tid & 255;      // output component owned by this thread
    const int p0   = blockIdx.x * PPB;

    // ---- stage A/B pair-split: half h stages pairs 4h..4h+3 at component i ----
    {
        const float* Ap = A + (size_t)(p0 + 4 * half) * NCOMP + i;
        const float* Bp = B + (size_t)(p0 + 4 * half) * NCOMP + i;
        float4 va, vb;
        va.x = Ap[0 * NCOMP]; va.y = Ap[1 * NCOMP]; va.z = Ap[2 * NCOMP]; va.w = Ap[3 * NCOMP];
        vb.x = Bp[0 * NCOMP]; vb.y = Bp[1 * NCOMP]; vb.z = Bp[2 * NCOMP]; vb.w = Bp[3 * NCOMP];
        (half ? As1 : As0)[i] = va;
        (half ? Bs1 : Bs0)[i] = vb;
    }
    // ---- stage tables: 2048 words each = 512 uint4, one per thread per table ----
    reinterpret_cast<uint4*>(Ssh)[tid] = reinterpret_cast<const uint4*>(g_sgn)[tid];
    reinterpret_cast<uint4*>(Wsh)[tid] = reinterpret_cast<const uint4*>(g_wed)[tid];
    reinterpret_cast<uint4*>(Ish)[tid] = reinterpret_cast<const uint4*>(g_inn)[tid];
    __syncthreads();

    const int lane  = i & 31;
    const int shamt = 31 - lane;
    const uint32_t* __restrict__ Srow = Ssh + ((i >> 5) << 8);
    const uint32_t* __restrict__ Wrow = Wsh + ((i >> 5) << 8);
    const uint32_t* __restrict__ Irow = Ish + ((i >> 5) << 8);
    const int jbase = half << 7;

    // Packed accumulators: pairs 2-wide per 64-bit reg (4 per product = 8 pairs)
    unsigned long long G0 = 0, G1 = 0, G2 = 0, G3 = 0;
    unsigned long long W0 = 0, W1 = 0, W2 = 0, W3 = 0;
    unsigned long long I0 = 0, I1 = 0, I2 = 0, I3 = 0;

#pragma unroll 4
    for (int j4 = 0; j4 < 32; ++j4) {
        const int jb = jbase + (j4 << 2);
        const uint4 s4 = *reinterpret_cast<const uint4*>(Srow + jb);
        const uint4 w4 = *reinterpret_cast<const uint4*>(Wrow + jb);
        const uint4 i4 = *reinterpret_cast<const uint4*>(Irow + jb);

#define DO_J(JOFF, SW, WD, ID)                                                     \
        {                                                                          \
            const int jj = jb + (JOFF);                                            \
            const int kx = jj ^ i;                                                 \
            const uint32_t sm = ((SW) << shamt) & 0x80000000u;                     \
            unsigned long long sm2;                                                \
            asm("mov.b64 %0, {%1,%1};" : "=l"(sm2) : "r"(sm));                     \
            const int wsig = (int)((WD) << shamt);  /* bit31 = wedge flag */       \
            const int isig = (int)((ID) << shamt);  /* bit31 = inner flag */       \
            const ulonglong2 av0 = *reinterpret_cast<const ulonglong2*>(&As0[jj]); \
            const ulonglong2 av1 = *reinterpret_cast<const ulonglong2*>(&As1[jj]); \
            const ulonglong2 bv0 = *reinterpret_cast<const ulonglong2*>(&Bs0[kx]); \
            const ulonglong2 bv1 = *reinterpret_cast<const ulonglong2*>(&Bs1[kx]); \
            const unsigned long long a0 = av0.x ^ sm2;                             \
            const unsigned long long a1 = av0.y ^ sm2;                             \
            const unsigned long long a2 = av1.x ^ sm2;                             \
            const unsigned long long a3 = av1.y ^ sm2;                             \
            asm("fma.rn.f32x2 %0, %4, %5, %0;\n\t"                                 \
                "fma.rn.f32x2 %1, %6, %7, %1;\n\t"                                 \
                "fma.rn.f32x2 %2, %8, %9, %2;\n\t"                                 \
                "fma.rn.f32x2 %3, %10, %11, %3;"                                   \
                : "+l"(G0), "+l"(G1), "+l"(G2), "+l"(G3)                           \
                : "l"(a0), "l"(bv0.x), "l"(a1), "l"(bv0.y),                        \
                  "l"(a2), "l"(bv1.x), "l"(a3), "l"(bv1.y));                       \
            asm("{\n\t"                                                            \
                ".reg .pred p;\n\t"                                                \
                "setp.lt.s32 p, %12, 0;\n\t"                                       \
                "@p fma.rn.f32x2 %0, %4, %5, %0;\n\t"                              \
                "@p fma.rn.f32x2 %1, %6, %7, %1;\n\t"                              \
                "@p fma.rn.f32x2 %2, %8, %9, %2;\n\t"                              \
                "@p fma.rn.f32x2 %3, %10, %11, %3;\n\t"                            \
                "}"                                                                \
                : "+l"(W0), "+l"(W1), "+l"(W2), "+l"(W3)                           \
                : "l"(a0), "l"(bv0.x), "l"(a1), "l"(bv0.y),                        \
                  "l"(a2), "l"(bv1.x), "l"(a3), "l"(bv1.y), "r"(wsig));            \
            asm("{\n\t"                                                            \
                ".reg .pred p;\n\t"                                                \
                "setp.lt.s32 p, %12, 0;\n\t"                                       \
                "@p fma.rn.f32x2 %0, %4, %5, %0;\n\t"                              \
                "@p fma.rn.f32x2 %1, %6, %7, %1;\n\t"                              \
                "@p fma.rn.f32x2 %2, %8, %9, %2;\n\t"                              \
                "@p fma.rn.f32x2 %3, %10, %11, %3;\n\t"                            \
                "}"                                                                \
                : "+l"(I0), "+l"(I1), "+l"(I2), "+l"(I3)                           \
                : "l"(a0), "l"(bv0.x), "l"(a1), "l"(bv0.y),                        \
                  "l"(a2), "l"(bv1.x), "l"(a3), "l"(bv1.y), "r"(isig));            \
        }

        DO_J(0, s4.x, w4.x, i4.x);
        DO_J(1, s4.y, w4.y, i4.y);
        DO_J(2, s4.z, w4.z, i4.z);
        DO_J(3, s4.w, w4.w, i4.w);
#undef DO_J
    }

    // ---- cross-half reduction (Red reuses sign-table smem) + store ----
    __syncthreads();

    const size_t plane = (size_t)npairs * NCOMP;
    float* __restrict__ og = out + (size_t)p0 * NCOMP + i;

#define LO(x) __uint_as_float((uint32_t)(x))
#define HI(x) __uint_as_float((uint32_t)((x) >> 32))
#define ROUND(V0, V1, V2, V3, DST)                                              \
    {                                                                           \
        if (half) {                                                             \
            Red[i * 2 + 0] = make_float4(LO(V0), HI(V0), LO(V1), HI(V1));       \
            Red[i * 2 + 1] = make_float4(LO(V2), HI(V2), LO(V3), HI(V3));       \
        }                                                                       \
        __syncthreads();                                                        \
        if (!half) {                                                            \
            const float4 r0 = Red[i * 2 + 0];                                   \
            const float4 r1 = Red[i * 2 + 1];                                   \
            (DST)[0 * NCOMP] = LO(V0) + r0.x; (DST)[1 * NCOMP] = HI(V0) + r0.y; \
            (DST)[2 * NCOMP] = LO(V1) + r0.z; (DST)[3 * NCOMP] = HI(V1) + r0.w; \
            (DST)[4 * NCOMP] = LO(V2) + r1.x; (DST)[5 * NCOMP] = HI(V2) + r1.y; \
            (DST)[6 * NCOMP] = LO(V3) + r1.z; (DST)[7 * NCOMP] = HI(V3) + r1.w; \
        }                                                                       \
        __syncthreads();                                                        \
    }

    ROUND(G0, G1, G2, G3, og)
    ROUND(W0, W1, W2, W3, og + plane)
    ROUND(I0, I1, I2, I3, og + 2 * plane)
#undef ROUND
#undef LO
#undef HI
}

extern "C" void kernel_launch(void* const* d_in, const int* in_sizes, int n_in,
                              void* d_out, int out_size)
{
    const float* A = (const float*)d_in[0];
    const float* B = (const float*)d_in[1];
    float* out = (float*)d_out;

    const int npairs = in_sizes[0] / NCOMP;   // 1024

    build_tables_kernel<<<256, 256>>>();
    clifford_kernel<<<npairs / PPB, TPB>>>(A, B, out, npairs);
}

// round 8
// speedup vs baseline: 1.5183x; 1.5183x over previous
#include <cuda_runtime.h>
#include <stdint.h>

#define NCOMP 256
#define PPB   8     // pairs per block
#define TPB   512   // two j-halves x 256 components

// Bit-packed tables indexed [ihi*256 + j], bit L refers to i = ihi*32 + L:
//   g_sgn: 1 iff sign(j, j^i) == -1
//   g_inn: 1 iff inner term ((j&i)==0 or i subset of j)
__device__ uint32_t g_sgn[8 * 256];
__device__ uint32_t g_inn[8 * 256];

__global__ void build_tables_kernel() {
    int t    = blockIdx.x * blockDim.x + threadIdx.x;   // 0..65535
    int lane = t & 31;
    int j    = (t >> 5) & 255;
    int ihi  = t >> 13;
    int i    = (ihi << 5) | lane;
    int k    = j ^ i;
    int par  = 0;
#pragma unroll
    for (int d = 1; d < 8; ++d) par ^= __popc((j >> d) & k);
    unsigned ws = __ballot_sync(0xFFFFFFFFu, par & 1);
    unsigned wi = __ballot_sync(0xFFFFFFFFu, ((j & i) == 0) || ((i & ~j & 255) == 0));
    if (lane == 0) {
        g_sgn[(ihi << 8) + j] = ws;
        g_inn[(ihi << 8) + j] = wi;
    }
}

__global__ __launch_bounds__(TPB, 1) void clifford_kernel(
    const float* __restrict__ A, const float* __restrict__ B,
    float* __restrict__ out, int npairs)
{
    // 40 KB pool:
    //   [0KB)  As0  float4[256]  pairs 0..3 of A at component j
    //   [4KB)  As1  float4[256]  pairs 4..7
    //   [8KB)  Bp0  float4[256]  pairs 0..3 of B (+)
    //   [12KB) Bp1  float4[256]  pairs 4..7 (+)
    //   [16KB) Bn0  float4[256]  pairs 0..3 of B negated
    //   [20KB) Bn1  float4[256]  pairs 4..7 negated
    //   [24KB) Ssh  sign table (8KB) -- reused as Red after the loop
    //   [32KB) Ish  inner table (8KB)
    __shared__ __align__(16) unsigned char pool[40960];
    float4*   As0 = reinterpret_cast<float4*>(pool);
    float4*   As1 = reinterpret_cast<float4*>(pool + 4096);
    uint32_t* Ssh = reinterpret_cast<uint32_t*>(pool + 24576);
    uint32_t* Ish = reinterpret_cast<uint32_t*>(pool + 32768);
    float4*   Red = reinterpret_cast<float4*>(pool + 24576);

    const int tid  = threadIdx.x;
    const int half = tid >> 8;       // 0: j in [0,128)   1: j in [128,256)
    const int i    = tid & 255;      // output component owned by this thread
    const int p0   = blockIdx.x * PPB;

    // ---- stage A/B pair-split: half h stages pairs 4h..4h+3 at component i ----
    {
        const float* Ap = A + (size_t)(p0 + 4 * half) * NCOMP + i;
        const float* Bp = B + (size_t)(p0 + 4 * half) * NCOMP + i;
        float4 va, vb, vn;
        va.x = Ap[0 * NCOMP]; va.y = Ap[1 * NCOMP]; va.z = Ap[2 * NCOMP]; va.w = Ap[3 * NCOMP];
        vb.x = Bp[0 * NCOMP]; vb.y = Bp[1 * NCOMP]; vb.z = Bp[2 * NCOMP]; vb.w = Bp[3 * NCOMP];
        vn.x = -vb.x; vn.y = -vb.y; vn.z = -vb.z; vn.w = -vb.w;
        *reinterpret_cast<float4*>(pool + (half ? 4096 : 0) + i * 16)           = va;
        *reinterpret_cast<float4*>(pool + 8192  + (half ? 4096 : 0) + i * 16)   = vb;
        *reinterpret_cast<float4*>(pool + 16384 + (half ? 4096 : 0) + i * 16)   = vn;
    }
    // ---- stage tables: 2048 words each = 512 uint4, one per thread per table ----
    reinterpret_cast<uint4*>(Ssh)[tid] = reinterpret_cast<const uint4*>(g_sgn)[tid];
    reinterpret_cast<uint4*>(Ish)[tid] = reinterpret_cast<const uint4*>(g_inn)[tid];
    __syncthreads();

    const int lane  = i & 31;
    const int shamt = 31 - lane;
    const int notI  = (~i) & 255;
    const uint32_t* __restrict__ Srow = Ssh + ((i >> 5) << 8);
    const uint32_t* __restrict__ Irow = Ish + ((i >> 5) << 8);
    const int jbase = half << 7;

    float g0=0.f,g1=0.f,g2=0.f,g3=0.f,g4=0.f,g5=0.f,g6=0.f,g7=0.f;   // geometric
    float w0=0.f,w1=0.f,w2=0.f,w3=0.f,w4=0.f,w5=0.f,w6=0.f,w7=0.f;   // wedge
    float n0=0.f,n1=0.f,n2=0.f,n3=0.f,n4=0.f,n5=0.f,n6=0.f,n7=0.f;   // inner

#pragma unroll 4
    for (int j4 = 0; j4 < 32; ++j4) {
        const int jb = jbase + (j4 << 2);
        const uint4 s4 = *reinterpret_cast<const uint4*>(Srow + jb);
        const uint4 i4 = *reinterpret_cast<const uint4*>(Irow + jb);

#define DO_J(JOFF, SW, ID)                                                      \
        {                                                                       \
            const int      jj  = jb + (JOFF);                                   \
            const int      kx  = jj ^ i;                                        \
            /* sign-selected B base: bit31 of (SW<<shamt) picks negated copy */ \
            const uint32_t boff = (((int)((SW) << shamt) < 0) ? 16384u : 8192u) \
                                  + (uint32_t)(kx << 4);                        \
            const bool     wed = ((jj & notI) == 0);                            \
            const bool     inn = ((int)((ID) << shamt) < 0);                    \
            const float4 a0 = As0[jj];                                          \
            const float4 a1 = As1[jj];                                          \
            const float4 b0 = *reinterpret_cast<const float4*>(pool + boff);    \
            const float4 b1 = *reinterpret_cast<const float4*>(pool + boff + 4096); \
            g0 = fmaf(a0.x, b0.x, g0); g1 = fmaf(a0.y, b0.y, g1);               \
            g2 = fmaf(a0.z, b0.z, g2); g3 = fmaf(a0.w, b0.w, g3);               \
            g4 = fmaf(a1.x, b1.x, g4); g5 = fmaf(a1.y, b1.y, g5);               \
            g6 = fmaf(a1.z, b1.z, g6); g7 = fmaf(a1.w, b1.w, g7);               \
            if (wed) {                                                          \
                w0 = fmaf(a0.x, b0.x, w0); w1 = fmaf(a0.y, b0.y, w1);           \
                w2 = fmaf(a0.z, b0.z, w2); w3 = fmaf(a0.w, b0.w, w3);           \
                w4 = fmaf(a1.x, b1.x, w4); w5 = fmaf(a1.y, b1.y, w5);           \
                w6 = fmaf(a1.z, b1.z, w6); w7 = fmaf(a1.w, b1.w, w7);           \
            }                                                                   \
            if (inn) {                                                          \
                n0 = fmaf(a0.x, b0.x, n0); n1 = fmaf(a0.y, b0.y, n1);           \
                n2 = fmaf(a0.z, b0.z, n2); n3 = fmaf(a0.w, b0.w, n3);           \
                n4 = fmaf(a1.x, b1.x, n4); n5 = fmaf(a1.y, b1.y, n5);           \
                n6 = fmaf(a1.z, b1.z, n6); n7 = fmaf(a1.w, b1.w, n7);           \
            }                                                                   \
        }

        DO_J(0, s4.x, i4.x);
        DO_J(1, s4.y, i4.y);
        DO_J(2, s4.z, i4.z);
        DO_J(3, s4.w, i4.w);
#undef DO_J
    }

    // ---- cross-half reduction (Red reuses the sign-table smem) + store ----
    __syncthreads();

    const size_t plane = (size_t)npairs * NCOMP;
    float* __restrict__ og = out + (size_t)p0 * NCOMP + i;

#define ROUND(V0,V1,V2,V3,V4,V5,V6,V7, DST)                                     \
    {                                                                           \
        if (half) {                                                             \
            Red[i * 2 + 0] = make_float4(V0, V1, V2, V3);                       \
            Red[i * 2 + 1] = make_float4(V4, V5, V6, V7);                       \
        }                                                                       \
        __syncthreads();                                                        \
        if (!half) {                                                            \
            const float4 r0 = Red[i * 2 + 0];                                   \
            const float4 r1 = Red[i * 2 + 1];                                   \
            (DST)[0 * NCOMP] = V0 + r0.x; (DST)[1 * NCOMP] = V1 + r0.y;         \
            (DST)[2 * NCOMP] = V2 + r0.z; (DST)[3 * NCOMP] = V3 + r0.w;         \
            (DST)[4 * NCOMP] = V4 + r1.x; (DST)[5 * NCOMP] = V5 + r1.y;         \
            (DST)[6 * NCOMP] = V6 + r1.z; (DST)[7 * NCOMP] = V7 + r1.w;         \
        }                                                                       \
        __syncthreads();                                                        \
    }

    ROUND(g0,g1,g2,g3,g4,g5,g6,g7, og)
    ROUND(w0,w1,w2,w3,w4,w5,w6,w7, og + plane)
    ROUND(n0,n1,n2,n3,n4,n5,n6,n7, og + 2 * plane)
#undef ROUND
}

extern "C" void kernel_launch(void* const* d_in, const int* in_sizes, int n_in,
                              void* d_out, int out_size)
{
    const float* A = (const float*)d_in[0];
    const float* B = (const float*)d_in[1];
    float* out = (float*)d_out;

    const int npairs = in_sizes[0] / NCOMP;   // 1024

    build_tables_kernel<<<256, 256>>>();
    clifford_kernel<<<npairs / PPB, TPB>>>(A, B, out, npairs);
}